// round 2
// baseline (speedup 1.0000x reference)
#include <cuda_runtime.h>
#include <math_constants.h>

// Problem constants
#define Bb 2
#define Ss 4096
#define Ee 512
#define Hh 8
#define Dd 64
#define HDv 512   // H*D

// Scratch (device globals; no allocation allowed)
__device__ float Qg[Bb * Ss * HDv];
__device__ float Kg[Bb * Ss * HDv];
__device__ float Vg[Bb * Ss * HDv];
__device__ float Og[Bb * Ss * HDv];

// ---------------------------------------------------------------------------
// SGEMM: C[M,512] = A[M,512] @ B[512,512], M multiple of 128.
// 128x128 tile, BK=8, 256 threads, 8x8 per thread.
// ---------------------------------------------------------------------------
__global__ __launch_bounds__(256) void sgemm_k512(
    const float* __restrict__ A, const float* __restrict__ Bw,
    float* __restrict__ C)
{
    __shared__ float As[8][128];
    __shared__ float Bs[8][128];

    const int tid = threadIdx.x;
    const int tx = tid & 15;
    const int ty = tid >> 4;
    const int bn = blockIdx.x * 128;
    const int bm = blockIdx.y * 128;

    const int arow = tid >> 1;         // 0..127
    const int acol = (tid & 1) << 2;   // 0 or 4
    const int brow = tid >> 5;         // 0..7
    const int bcol = (tid & 31) << 2;  // 0..124

    const float* Ap = A + (size_t)(bm + arow) * 512 + acol;
    const float* Bp = Bw + (size_t)brow * 512 + bn + bcol;

    float acc[8][8];
#pragma unroll
    for (int i = 0; i < 8; ++i)
#pragma unroll
        for (int j = 0; j < 8; ++j) acc[i][j] = 0.f;

    for (int k0 = 0; k0 < 512; k0 += 8) {
        float4 av = *(const float4*)Ap;  Ap += 8;
        float4 bv = *(const float4*)Bp;  Bp += 8 * 512;
        As[acol + 0][arow] = av.x;
        As[acol + 1][arow] = av.y;
        As[acol + 2][arow] = av.z;
        As[acol + 3][arow] = av.w;
        *(float4*)&Bs[brow][bcol] = bv;
        __syncthreads();
#pragma unroll
        for (int kk = 0; kk < 8; ++kk) {
            float ar[8], br[8];
            *(float4*)(ar)     = *(const float4*)&As[kk][ty * 8];
            *(float4*)(ar + 4) = *(const float4*)&As[kk][ty * 8 + 4];
            *(float4*)(br)     = *(const float4*)&Bs[kk][tx * 8];
            *(float4*)(br + 4) = *(const float4*)&Bs[kk][tx * 8 + 4];
#pragma unroll
            for (int i = 0; i < 8; ++i)
#pragma unroll
                for (int j = 0; j < 8; ++j)
                    acc[i][j] += ar[i] * br[j];
        }
        __syncthreads();
    }

    float* Cp = C + (size_t)(bm + ty * 8) * 512 + bn + tx * 8;
#pragma unroll
    for (int i = 0; i < 8; ++i) {
        *(float4*)(Cp + (size_t)i * 512)     =
            make_float4(acc[i][0], acc[i][1], acc[i][2], acc[i][3]);
        *(float4*)(Cp + (size_t)i * 512 + 4) =
            make_float4(acc[i][4], acc[i][5], acc[i][6], acc[i][7]);
    }
}

// ---------------------------------------------------------------------------
// Flash attention: one block per (b, h, 64-row q tile). 256 threads.
// Online softmax over 64-wide k tiles. Mask is int32 (numpy bool widened):
// nonzero -> -1e10.
// smem: Qs[64][64] (transposed, Qs[d][r]), KVs[64][64] (K transposed /
// V natural), Ps[64][64] (transposed, Ps[k][r]); int32 mask tile (16 KB)
// staged in Ps before P is written. Total static smem = 48 KB.
// ---------------------------------------------------------------------------
__global__ __launch_bounds__(256) void flash_attn(
    const float* __restrict__ Q, const float* __restrict__ K,
    const float* __restrict__ V, const int* __restrict__ Mask,
    float* __restrict__ O)
{
    __shared__ float sm[3 * 64 * 64];
    float* Qs  = sm;
    float* KVs = sm + 64 * 64;
    float* Ps  = sm + 2 * 64 * 64;
    int* Ms = (int*)Ps;  // 16 KB int32 mask staging (pre-P phase)

    const int tid = threadIdx.x;
    const int tx = tid & 15;   // col group
    const int ty = tid >> 4;   // row group
    const int q0 = blockIdx.x * 64;
    const int h  = blockIdx.y;
    const int b  = blockIdx.z;

    const int row  = tid >> 2;  // 0..63  cooperative-load row
    const int quad = tid & 3;   // 0..3

    // Load Q tile transposed: Qs[d][r]
    {
        const float* qp = Q + (size_t)(b * Ss + q0 + row) * HDv + h * Dd + quad * 16;
#pragma unroll
        for (int i = 0; i < 4; ++i) {
            float4 v = *(const float4*)(qp + 4 * i);
            int d = quad * 16 + 4 * i;
            Qs[(d + 0) * 64 + row] = v.x;
            Qs[(d + 1) * 64 + row] = v.y;
            Qs[(d + 2) * 64 + row] = v.z;
            Qs[(d + 3) * 64 + row] = v.w;
        }
    }

    float m_i[4], l_i[4], acc[4][4];
#pragma unroll
    for (int ii = 0; ii < 4; ++ii) {
        m_i[ii] = -CUDART_INF_F;
        l_i[ii] = 0.f;
#pragma unroll
        for (int jj = 0; jj < 4; ++jj) acc[ii][jj] = 0.f;
    }

    const int* mbase = Mask + ((size_t)(b * Hh + h) * Ss + q0) * Ss;
    const float scale = 0.125f;  // 1/sqrt(64)

    for (int k0 = 0; k0 < Ss; k0 += 64) {
        __syncthreads();  // prior-iter Ps/KVs reads done

        // Load K tile transposed into KVs, stage int32 mask tile into Ms
        {
            const float* kp = K + (size_t)(b * Ss + k0 + row) * HDv + h * Dd + quad * 16;
#pragma unroll
            for (int i = 0; i < 4; ++i) {
                float4 v = *(const float4*)(kp + 4 * i);
                int d = quad * 16 + 4 * i;
                KVs[(d + 0) * 64 + row] = v.x;
                KVs[(d + 1) * 64 + row] = v.y;
                KVs[(d + 2) * 64 + row] = v.z;
                KVs[(d + 3) * 64 + row] = v.w;
            }
            const int* mrow = mbase + (size_t)row * Ss + k0 + quad * 16;
#pragma unroll
            for (int i = 0; i < 4; ++i) {
                int4 mv = *(const int4*)(mrow + 4 * i);
                *(int4*)(Ms + row * 64 + quad * 16 + 4 * i) = mv;
            }
        }
        __syncthreads();

        // Grab my 16 mask words into registers (before Ps is overwritten by P)
        int mreg[4][4];
#pragma unroll
        for (int ii = 0; ii < 4; ++ii) {
            int4 mv = *(const int4*)(Ms + (4 * ty + ii) * 64 + 4 * tx);
            mreg[ii][0] = mv.x; mreg[ii][1] = mv.y;
            mreg[ii][2] = mv.z; mreg[ii][3] = mv.w;
        }

        // S = Q K^T  (64x64 tile, 4x4 per thread)
        float s[4][4];
#pragma unroll
        for (int ii = 0; ii < 4; ++ii)
#pragma unroll
            for (int jj = 0; jj < 4; ++jj) s[ii][jj] = 0.f;

#pragma unroll 16
        for (int d = 0; d < 64; ++d) {
            float4 qv = *(const float4*)(Qs + d * 64 + 4 * ty);
            float4 kv = *(const float4*)(KVs + d * 64 + 4 * tx);
            float qr[4] = {qv.x, qv.y, qv.z, qv.w};
            float kr[4] = {kv.x, kv.y, kv.z, kv.w};
#pragma unroll
            for (int ii = 0; ii < 4; ++ii)
#pragma unroll
                for (int jj = 0; jj < 4; ++jj)
                    s[ii][jj] += qr[ii] * kr[jj];
        }

        // scale + mask (nonzero int -> -1e10)
#pragma unroll
        for (int ii = 0; ii < 4; ++ii) {
#pragma unroll
            for (int jj = 0; jj < 4; ++jj) {
                float v = s[ii][jj] * scale;
                if (mreg[ii][jj] != 0) v = -1e10f;
                s[ii][jj] = v;
            }
        }

        // online softmax (row reductions across the 16 tx lanes)
        float p[4][4];
#pragma unroll
        for (int ii = 0; ii < 4; ++ii) {
            float mt = fmaxf(fmaxf(s[ii][0], s[ii][1]), fmaxf(s[ii][2], s[ii][3]));
#pragma unroll
            for (int off = 8; off; off >>= 1)
                mt = fmaxf(mt, __shfl_xor_sync(0xffffffffu, mt, off));
            float mnew = fmaxf(m_i[ii], mt);
            float corr = __expf(m_i[ii] - mnew);
            m_i[ii] = mnew;
            float rs = 0.f;
#pragma unroll
            for (int jj = 0; jj < 4; ++jj) {
                float e = __expf(s[ii][jj] - mnew);
                p[ii][jj] = e;
                rs += e;
            }
#pragma unroll
            for (int off = 8; off; off >>= 1)
                rs += __shfl_xor_sync(0xffffffffu, rs, off);
            l_i[ii] = l_i[ii] * corr + rs;
#pragma unroll
            for (int jj = 0; jj < 4; ++jj) acc[ii][jj] *= corr;
        }

        __syncthreads();  // mask/K reads done; Ps & KVs reusable

        // Write P transposed: Ps[k][r]
#pragma unroll
        for (int jj = 0; jj < 4; ++jj) {
            float4 pv = make_float4(p[0][jj], p[1][jj], p[2][jj], p[3][jj]);
            *(float4*)(Ps + (4 * tx + jj) * 64 + 4 * ty) = pv;
        }
        // Load V tile natural: KVs[k][c]
        {
            const float* vp = V + (size_t)(b * Ss + k0 + row) * HDv + h * Dd + quad * 16;
#pragma unroll
            for (int i = 0; i < 4; ++i) {
                float4 v = *(const float4*)(vp + 4 * i);
                *(float4*)(KVs + row * 64 + quad * 16 + 4 * i) = v;
            }
        }
        __syncthreads();

        // O += P @ V
#pragma unroll 16
        for (int k = 0; k < 64; ++k) {
            float4 pv = *(const float4*)(Ps + k * 64 + 4 * ty);
            float4 vv = *(const float4*)(KVs + k * 64 + 4 * tx);
            float pr[4] = {pv.x, pv.y, pv.z, pv.w};
            float vr[4] = {vv.x, vv.y, vv.z, vv.w};
#pragma unroll
            for (int ii = 0; ii < 4; ++ii)
#pragma unroll
                for (int jj = 0; jj < 4; ++jj)
                    acc[ii][jj] += pr[ii] * vr[jj];
        }
    }

    // normalize and write
    float* op = O + (size_t)(b * Ss + q0) * HDv + h * Dd;
#pragma unroll
    for (int ii = 0; ii < 4; ++ii) {
        float inv = 1.f / l_i[ii];
        *(float4*)(op + (size_t)(4 * ty + ii) * HDv + 4 * tx) =
            make_float4(acc[ii][0] * inv, acc[ii][1] * inv,
                        acc[ii][2] * inv, acc[ii][3] * inv);
    }
}

// ---------------------------------------------------------------------------
// Launch
// ---------------------------------------------------------------------------
extern "C" void kernel_launch(void* const* d_in, const int* in_sizes, int n_in,
                              void* d_out, int out_size)
{
    (void)in_sizes; (void)n_in; (void)out_size;
    const float* queries = (const float*)d_in[0];
    const float* keys    = (const float*)d_in[1];
    const float* values  = (const float*)d_in[2];
    const int*   mask    = (const int*)d_in[3];
    const float* Wq = (const float*)d_in[4];
    const float* Wk = (const float*)d_in[5];
    const float* Wv = (const float*)d_in[6];
    const float* Wo = (const float*)d_in[7];

    void *qp, *kp, *vp, *op;
    cudaGetSymbolAddress(&qp, Qg);
    cudaGetSymbolAddress(&kp, Kg);
    cudaGetSymbolAddress(&vp, Vg);
    cudaGetSymbolAddress(&op, Og);

    dim3 gg(512 / 128, (Bb * Ss) / 128);  // (4, 64)
    dim3 gt(256);

    sgemm_k512<<<gg, gt>>>(queries, Wq, (float*)qp);
    sgemm_k512<<<gg, gt>>>(keys,    Wk, (float*)kp);
    sgemm_k512<<<gg, gt>>>(values,  Wv, (float*)vp);

    flash_attn<<<dim3(Ss / 64, Hh, Bb), 256>>>(
        (const float*)qp, (const float*)kp, (const float*)vp, mask, (float*)op);

    sgemm_k512<<<gg, gt>>>((const float*)op, Wo, (float*)d_out);
}

// round 3
// speedup vs baseline: 1.0575x; 1.0575x over previous
#include <cuda_runtime.h>
#include <math_constants.h>

// Problem constants
#define Bb 2
#define Ss 4096
#define Hh 8
#define HDv 512   // H*D (D=64)

typedef unsigned long long ull;

// Scratch (device globals; no allocation allowed)
__device__ float Qg[Bb * Ss * HDv];
__device__ float Kg[Bb * Ss * HDv];
__device__ float Vg[Bb * Ss * HDv];
__device__ float Og[Bb * Ss * HDv];

// ---- packed f32x2 helpers -------------------------------------------------
__device__ __forceinline__ ull pk2(float a, float b) {
    ull r; asm("mov.b64 %0, {%1, %2};" : "=l"(r) : "f"(a), "f"(b)); return r;
}
__device__ __forceinline__ void upk(ull v, float& a, float& b) {
    asm("mov.b64 {%0, %1}, %2;" : "=f"(a), "=f"(b) : "l"(v));
}
__device__ __forceinline__ ull f2fma(ull a, ull b, ull c) {
    ull d; asm("fma.rn.f32x2 %0, %1, %2, %3;" : "=l"(d) : "l"(a), "l"(b), "l"(c));
    return d;
}
__device__ __forceinline__ ull f2mul(ull a, ull b) {
    ull d; asm("mul.rn.f32x2 %0, %1, %2;" : "=l"(d) : "l"(a), "l"(b));
    return d;
}

// ---------------------------------------------------------------------------
// SGEMM: C[M,512] = A[M,512] @ B[512,512], M multiple of 128.
// 128x128 tile, BK=8, 256 threads, 8x8 per thread, FFMA2 inner product.
// ---------------------------------------------------------------------------
__global__ __launch_bounds__(256) void sgemm_k512(
    const float* __restrict__ A, const float* __restrict__ Bw,
    float* __restrict__ C)
{
    __shared__ float As[8][128];
    __shared__ float Bs[8][128];

    const int tid = threadIdx.x;
    const int tx = tid & 15;
    const int ty = tid >> 4;
    const int bn = blockIdx.x * 128;
    const int bm = blockIdx.y * 128;

    const int arow = tid >> 1;         // 0..127
    const int acol = (tid & 1) << 2;   // 0 or 4
    const int brow = tid >> 5;         // 0..7
    const int bcol = (tid & 31) << 2;  // 0..124

    const float* Ap = A + (size_t)(bm + arow) * 512 + acol;
    const float* Bp = Bw + (size_t)brow * 512 + bn + bcol;

    ull acc2[8][4];
#pragma unroll
    for (int i = 0; i < 8; ++i)
#pragma unroll
        for (int j = 0; j < 4; ++j) acc2[i][j] = 0ull;

    for (int k0 = 0; k0 < 512; k0 += 8) {
        float4 av = *(const float4*)Ap;  Ap += 8;
        float4 bv = *(const float4*)Bp;  Bp += 8 * 512;
        As[acol + 0][arow] = av.x;
        As[acol + 1][arow] = av.y;
        As[acol + 2][arow] = av.z;
        As[acol + 3][arow] = av.w;
        *(float4*)&Bs[brow][bcol] = bv;
        __syncthreads();
#pragma unroll
        for (int kk = 0; kk < 8; ++kk) {
            float ar[8];
            *(float4*)(ar)     = *(const float4*)&As[kk][ty * 8];
            *(float4*)(ar + 4) = *(const float4*)&As[kk][ty * 8 + 4];
            ulonglong2 b01 = *(const ulonglong2*)&Bs[kk][tx * 8];
            ulonglong2 b23 = *(const ulonglong2*)&Bs[kk][tx * 8 + 4];
#pragma unroll
            for (int i = 0; i < 8; ++i) {
                ull ap = pk2(ar[i], ar[i]);
                acc2[i][0] = f2fma(ap, b01.x, acc2[i][0]);
                acc2[i][1] = f2fma(ap, b01.y, acc2[i][1]);
                acc2[i][2] = f2fma(ap, b23.x, acc2[i][2]);
                acc2[i][3] = f2fma(ap, b23.y, acc2[i][3]);
            }
        }
        __syncthreads();
    }

    float* Cp = C + (size_t)(bm + ty * 8) * 512 + bn + tx * 8;
#pragma unroll
    for (int i = 0; i < 8; ++i) {
        float c0, c1, c2, c3, c4, c5, c6, c7;
        upk(acc2[i][0], c0, c1); upk(acc2[i][1], c2, c3);
        upk(acc2[i][2], c4, c5); upk(acc2[i][3], c6, c7);
        *(float4*)(Cp + (size_t)i * 512)     = make_float4(c0, c1, c2, c3);
        *(float4*)(Cp + (size_t)i * 512 + 4) = make_float4(c4, c5, c6, c7);
    }
}

// ---------------------------------------------------------------------------
// Flash attention v2: one block per (b, h, 64-row q tile). 128 threads.
// Per-thread 8q x 4k register tile, FFMA2 GEMM cores.
// Dynamic smem 64 KB:
//   Qs  [64][64] f32  (transposed [d][q])          16 KB
//   KVs [64][64] f32  (K: [d][k] ; V: [k][d])      16 KB
//   Ps2 [64][64] b64  (P duplicated {p,p}, [q][k]) 32 KB
// Mask (int32, nonzero -> -1e10) loaded direct to registers via LDG.128.
// ---------------------------------------------------------------------------
__global__ void __launch_bounds__(128, 3) flash_attn(
    const float* __restrict__ Q, const float* __restrict__ K,
    const float* __restrict__ V, const int* __restrict__ Mask,
    float* __restrict__ O)
{
    extern __shared__ char dsm[];
    float* Qs  = (float*)dsm;                 // 16 KB
    float* KVs = (float*)(dsm + 16384);       // 16 KB
    ull*   Ps2 = (ull*)(dsm + 32768);         // 32 KB

    const int tid = threadIdx.x;
    const int tx = tid & 15;      // 4 k-cols (or d-cols) each
    const int ty = tid >> 4;      // 8 q-rows each (0..7)
    const int q0 = blockIdx.x * 64;
    const int h  = blockIdx.y;
    const int b  = blockIdx.z;

    const int row  = tid >> 1;        // 0..63 cooperative-load row
    const int half = (tid & 1) * 32;  // 32-col half

    // Load Q tile transposed: Qs[d][q]
    {
        const float* qp = Q + (size_t)(b * Ss + q0 + row) * HDv + h * 64 + half;
#pragma unroll
        for (int i = 0; i < 8; ++i) {
            float4 v = *(const float4*)(qp + 4 * i);
            int d = half + 4 * i;
            Qs[(d + 0) * 64 + row] = v.x;
            Qs[(d + 1) * 64 + row] = v.y;
            Qs[(d + 2) * 64 + row] = v.z;
            Qs[(d + 3) * 64 + row] = v.w;
        }
    }

    float m_i[8], l_i[8];
    ull acc2[8][2];
#pragma unroll
    for (int i = 0; i < 8; ++i) {
        m_i[i] = -CUDART_INF_F;
        l_i[i] = 0.f;
        acc2[i][0] = 0ull;
        acc2[i][1] = 0ull;
    }

    const int* mbase = Mask + ((size_t)(b * Hh + h) * Ss + q0) * Ss;

    for (int k0 = 0; k0 < Ss; k0 += 64) {
        __syncthreads();  // prev PV reads of KVs/Ps2 done (also covers Q store, iter 0)

        // Load K tile transposed: KVs[d][k]
        {
            const float* kp = K + (size_t)(b * Ss + k0 + row) * HDv + h * 64 + half;
#pragma unroll
            for (int i = 0; i < 8; ++i) {
                float4 v = *(const float4*)(kp + 4 * i);
                int d = half + 4 * i;
                KVs[(d + 0) * 64 + row] = v.x;
                KVs[(d + 1) * 64 + row] = v.y;
                KVs[(d + 2) * 64 + row] = v.z;
                KVs[(d + 3) * 64 + row] = v.w;
            }
        }
        __syncthreads();

        // ---- S = Q K^T : 8x4 per thread, packed pairs along k ----
        ull s2[8][2];
#pragma unroll
        for (int i = 0; i < 8; ++i) { s2[i][0] = 0ull; s2[i][1] = 0ull; }

#pragma unroll 4
        for (int d = 0; d < 64; ++d) {
            float qr[8];
            *(float4*)(qr)     = *(const float4*)&Qs[d * 64 + 8 * ty];
            *(float4*)(qr + 4) = *(const float4*)&Qs[d * 64 + 8 * ty + 4];
            ulonglong2 kk2 = *(const ulonglong2*)&KVs[d * 64 + 4 * tx];
#pragma unroll
            for (int i = 0; i < 8; ++i) {
                ull qq = pk2(qr[i], qr[i]);
                s2[i][0] = f2fma(qq, kk2.x, s2[i][0]);
                s2[i][1] = f2fma(qq, kk2.y, s2[i][1]);
            }
        }

        // Mask loads (direct from gmem, issued back-to-back for MLP)
        int4 mreg[8];
#pragma unroll
        for (int i = 0; i < 8; ++i)
            mreg[i] = *(const int4*)(mbase + (size_t)(8 * ty + i) * Ss + k0 + 4 * tx);

        // ---- softmax (online), write P duplicated to Ps2 ----
#pragma unroll
        for (int i = 0; i < 8; ++i) {
            float s0, s1, sv2, s3;
            upk(s2[i][0], s0, s1);
            upk(s2[i][1], sv2, s3);
            s0 = (mreg[i].x != 0) ? -1e10f : s0 * 0.125f;
            s1 = (mreg[i].y != 0) ? -1e10f : s1 * 0.125f;
            sv2 = (mreg[i].z != 0) ? -1e10f : sv2 * 0.125f;
            s3 = (mreg[i].w != 0) ? -1e10f : s3 * 0.125f;

            float mt = fmaxf(fmaxf(s0, s1), fmaxf(sv2, s3));
#pragma unroll
            for (int off = 8; off; off >>= 1)
                mt = fmaxf(mt, __shfl_xor_sync(0xffffffffu, mt, off));
            float mnew = fmaxf(m_i[i], mt);
            float corr = __expf(m_i[i] - mnew);
            m_i[i] = mnew;

            float p0 = __expf(s0 - mnew);
            float p1 = __expf(s1 - mnew);
            float p2v = __expf(sv2 - mnew);
            float p3 = __expf(s3 - mnew);
            float rs = (p0 + p1) + (p2v + p3);
#pragma unroll
            for (int off = 8; off; off >>= 1)
                rs += __shfl_xor_sync(0xffffffffu, rs, off);
            l_i[i] = l_i[i] * corr + rs;

            ull c2 = pk2(corr, corr);
            acc2[i][0] = f2mul(acc2[i][0], c2);
            acc2[i][1] = f2mul(acc2[i][1], c2);

            ulonglong2 w0, w1;
            w0.x = pk2(p0, p0);  w0.y = pk2(p1, p1);
            w1.x = pk2(p2v, p2v); w1.y = pk2(p3, p3);
            *(ulonglong2*)&Ps2[(8 * ty + i) * 64 + 4 * tx]     = w0;
            *(ulonglong2*)&Ps2[(8 * ty + i) * 64 + 4 * tx + 2] = w1;
        }

        __syncthreads();  // K reads done -> KVs reusable for V

        // Load V tile natural: KVs[k][d]
        {
            const float* vp = V + (size_t)(b * Ss + k0 + row) * HDv + h * 64 + half;
#pragma unroll
            for (int i = 0; i < 8; ++i)
                *(float4*)&KVs[row * 64 + half + 4 * i] = *(const float4*)(vp + 4 * i);
        }
        __syncthreads();  // V + Ps2 visible

        // ---- O += P @ V : packed pairs along d ----
#pragma unroll 4
        for (int k = 0; k < 64; ++k) {
            ulonglong2 vv = *(const ulonglong2*)&KVs[k * 64 + 4 * tx];
#pragma unroll
            for (int i = 0; i < 8; ++i) {
                ull pp = Ps2[(8 * ty + i) * 64 + k];
                acc2[i][0] = f2fma(pp, vv.x, acc2[i][0]);
                acc2[i][1] = f2fma(pp, vv.y, acc2[i][1]);
            }
        }
    }

    // normalize and write
#pragma unroll
    for (int i = 0; i < 8; ++i) {
        float inv = 1.f / l_i[i];
        float o0, o1, o2, o3;
        upk(acc2[i][0], o0, o1);
        upk(acc2[i][1], o2, o3);
        *(float4*)&O[(size_t)(b * Ss + q0 + 8 * ty + i) * HDv + h * 64 + 4 * tx] =
            make_float4(o0 * inv, o1 * inv, o2 * inv, o3 * inv);
    }
}

// ---------------------------------------------------------------------------
// Launch
// ---------------------------------------------------------------------------
extern "C" void kernel_launch(void* const* d_in, const int* in_sizes, int n_in,
                              void* d_out, int out_size)
{
    (void)in_sizes; (void)n_in; (void)out_size;
    const float* queries = (const float*)d_in[0];
    const float* keys    = (const float*)d_in[1];
    const float* values  = (const float*)d_in[2];
    const int*   mask    = (const int*)d_in[3];
    const float* Wq = (const float*)d_in[4];
    const float* Wk = (const float*)d_in[5];
    const float* Wv = (const float*)d_in[6];
    const float* Wo = (const float*)d_in[7];

    void *qp, *kp, *vp, *op;
    cudaGetSymbolAddress(&qp, Qg);
    cudaGetSymbolAddress(&kp, Kg);
    cudaGetSymbolAddress(&vp, Vg);
    cudaGetSymbolAddress(&op, Og);

    cudaFuncSetAttribute(flash_attn,
                         cudaFuncAttributeMaxDynamicSharedMemorySize, 65536);

    dim3 gg(512 / 128, (Bb * Ss) / 128);  // (4, 64)
    dim3 gt(256);

    sgemm_k512<<<gg, gt>>>(queries, Wq, (float*)qp);
    sgemm_k512<<<gg, gt>>>(keys,    Wk, (float*)kp);
    sgemm_k512<<<gg, gt>>>(values,  Wv, (float*)vp);

    flash_attn<<<dim3(Ss / 64, Hh, Bb), 128, 65536>>>(
        (const float*)qp, (const float*)kp, (const float*)vp, mask, (float*)op);

    sgemm_k512<<<gg, gt>>>((const float*)op, Wo, (float*)d_out);
}